// round 1
// baseline (speedup 1.0000x reference)
#include <cuda_runtime.h>
#include <cuda_bf16.h>

#define N 8192
#define BITS 16
#define NLAB 81
#define GAMMA 0.5f
#define ETA 0.5f
#define TILE 128
#define NCTA ((N/TILE)*(N/TILE))   // 64*64 = 4096

// scratch: packed label bitmasks + per-CTA partial sums
__device__ unsigned long long g_img_lo[N];
__device__ unsigned int       g_img_hi[N];
__device__ unsigned long long g_tex_lo[N];
__device__ unsigned int       g_tex_hi[N];
__device__ double             g_partial[NCTA];

// ---------------------------------------------------------------------------
// Kernel 1: pack 81-bit binary labels into (u64 lo, u32 hi) per row.
// sim(i,t) = ((img_lo[i] & tex_lo[t]) | (img_hi[i] & tex_hi[t])) != 0
// ---------------------------------------------------------------------------
__global__ void pack_labels_kernel(const int* __restrict__ img,
                                   const int* __restrict__ tex) {
    int i = blockIdx.x * blockDim.x + threadIdx.x;
    if (i >= N) return;
    unsigned long long ilo = 0ull, tlo = 0ull;
    unsigned int ihi = 0u, thi = 0u;
    const int* ir = img + (long long)i * NLAB;
    const int* tr = tex + (long long)i * NLAB;
#pragma unroll
    for (int c = 0; c < 64; c++) {
        ilo |= (unsigned long long)(ir[c] & 1) << c;
        tlo |= (unsigned long long)(tr[c] & 1) << c;
    }
#pragma unroll
    for (int c = 64; c < NLAB; c++) {
        ihi |= (unsigned int)(ir[c] & 1) << (c - 64);
        thi |= (unsigned int)(tr[c] & 1) << (c - 64);
    }
    g_img_lo[i] = ilo; g_img_hi[i] = ihi;
    g_tex_lo[i] = tlo; g_tex_hi[i] = thi;
}

// ---------------------------------------------------------------------------
// Kernel 2: main N x N pass. Each CTA owns a 128x128 theta tile.
// 256 threads as 16x16; each thread computes an 8x8 register sub-tile via
// outer-product accumulation over K=16, then applies
//   softplus(theta/2) - (sim ? theta : 0)
// and reduces to one double partial per CTA (deterministic).
// ---------------------------------------------------------------------------
__global__ __launch_bounds__(256, 2)
void theta_loss_kernel(const float* __restrict__ F,
                       const float* __restrict__ G) {
    __shared__ float sF[BITS][TILE];   // k-major F tile (rows i0..i0+127)
    __shared__ float sG[BITS][TILE];   // k-major G tile (cols t0..t0+127)
    __shared__ unsigned long long sIlo[TILE];
    __shared__ unsigned int       sIhi[TILE];
    __shared__ unsigned long long sTlo[TILE];
    __shared__ unsigned int       sThi[TILE];
    __shared__ float warp_sum[8];

    const int tid = threadIdx.x;
    const int i0 = blockIdx.y * TILE;
    const int t0 = blockIdx.x * TILE;

    // --- load tiles: thread loads 8 contiguous floats (row r, half h) ---
    {
        int r = tid >> 1;            // 0..127
        int h = (tid & 1) * 8;       // k offset 0 or 8
        const float4* fp = (const float4*)(F + (long long)(i0 + r) * BITS + h);
        const float4* gp = (const float4*)(G + (long long)(t0 + r) * BITS + h);
        float4 f0 = fp[0], f1 = fp[1];
        float4 g0 = gp[0], g1 = gp[1];
        sF[h + 0][r] = f0.x; sF[h + 1][r] = f0.y; sF[h + 2][r] = f0.z; sF[h + 3][r] = f0.w;
        sF[h + 4][r] = f1.x; sF[h + 5][r] = f1.y; sF[h + 6][r] = f1.z; sF[h + 7][r] = f1.w;
        sG[h + 0][r] = g0.x; sG[h + 1][r] = g0.y; sG[h + 2][r] = g0.z; sG[h + 3][r] = g0.w;
        sG[h + 4][r] = g1.x; sG[h + 5][r] = g1.y; sG[h + 6][r] = g1.z; sG[h + 7][r] = g1.w;
    }
    if (tid < TILE) {
        sIlo[tid] = g_img_lo[i0 + tid];
        sIhi[tid] = g_img_hi[i0 + tid];
    } else {
        int r = tid - TILE;
        sTlo[r] = g_tex_lo[t0 + r];
        sThi[r] = g_tex_hi[t0 + r];
    }
    __syncthreads();

    const int ty = tid >> 4;   // 0..15 -> row group
    const int tx = tid & 15;   // 0..15 -> col group

    float acc[8][8];
#pragma unroll
    for (int a = 0; a < 8; a++)
#pragma unroll
        for (int b = 0; b < 8; b++) acc[a][b] = 0.0f;

#pragma unroll
    for (int k = 0; k < BITS; k++) {
        float4 a0 = *(const float4*)&sF[k][ty * 8];
        float4 a1 = *(const float4*)&sF[k][ty * 8 + 4];
        float4 b0 = *(const float4*)&sG[k][tx * 8];
        float4 b1 = *(const float4*)&sG[k][tx * 8 + 4];
        float av[8] = {a0.x, a0.y, a0.z, a0.w, a1.x, a1.y, a1.z, a1.w};
        float bv[8] = {b0.x, b0.y, b0.z, b0.w, b1.x, b1.y, b1.z, b1.w};
#pragma unroll
        for (int a = 0; a < 8; a++)
#pragma unroll
            for (int b = 0; b < 8; b++)
                acc[a][b] = fmaf(av[a], bv[b], acc[a][b]);
    }

    // --- epilogue: softplus + sim-masked subtraction ---
    float sum = 0.0f;
#pragma unroll
    for (int a = 0; a < 8; a++) {
        unsigned long long ilo = sIlo[ty * 8 + a];
        unsigned int       ihi = sIhi[ty * 8 + a];
#pragma unroll
        for (int b = 0; b < 8; b++) {
            float th = acc[a][b];
            unsigned long long m =
                (ilo & sTlo[tx * 8 + b]) |
                (unsigned long long)(ihi & sThi[tx * 8 + b]);
            float x = 0.5f * th;
            // |x| <= ~15 here, so 1 + exp(x) never overflows fp32
            float sp = __logf(1.0f + __expf(x));
            sum += sp - (m != 0ull ? th : 0.0f);
        }
    }

    // --- deterministic CTA reduction ---
#pragma unroll
    for (int off = 16; off > 0; off >>= 1)
        sum += __shfl_down_sync(0xffffffffu, sum, off);
    if ((tid & 31) == 0) warp_sum[tid >> 5] = sum;
    __syncthreads();
    if (tid == 0) {
        float s = 0.0f;
#pragma unroll
        for (int w = 0; w < 8; w++) s += warp_sum[w];
        g_partial[blockIdx.y * gridDim.x + blockIdx.x] = (double)s;
    }
}

// ---------------------------------------------------------------------------
// Kernel 3: finalize. One CTA sums the 4096 CTA partials (fixed order),
// computes term2/term3 (O(N*16)), writes the scalar.
// ---------------------------------------------------------------------------
__global__ void finalize_kernel(const float* __restrict__ F,
                                const float* __restrict__ G,
                                const float* __restrict__ B,
                                float* __restrict__ out) {
    __shared__ double sh[256];
    int t = threadIdx.x;

    double acc = 0.0;
    for (int p = t; p < NCTA; p += 256) acc += g_partial[p];

    for (int i = t; i < N; i += 256) {
        const float* fr = F + (long long)i * BITS;
        const float* gr = G + (long long)i * BITS;
        const float* br = B + (long long)i * BITS;
        float q = 0.0f, sf = 0.0f, sg = 0.0f;
#pragma unroll
        for (int k = 0; k < BITS; k++) {
            float f = fr[k], g = gr[k], b = br[k];
            float df = b - f, dg = b - g;
            q = fmaf(df, df, q);
            q = fmaf(dg, dg, q);
            sf += f;
            sg += g;
        }
        acc += (double)(GAMMA * q + ETA * (sf * sf + sg * sg));
    }

    sh[t] = acc;
    __syncthreads();
    for (int s = 128; s > 0; s >>= 1) {
        if (t < s) sh[t] += sh[t + s];
        __syncthreads();
    }
    if (t == 0) out[0] = (float)sh[0];
}

// ---------------------------------------------------------------------------
extern "C" void kernel_launch(void* const* d_in, const int* in_sizes, int n_in,
                              void* d_out, int out_size) {
    const float* F = (const float*)d_in[0];
    const float* G = (const float*)d_in[1];
    const float* B = (const float*)d_in[2];
    const int* img = (const int*)d_in[3];
    const int* tex = (const int*)d_in[4];
    float* out = (float*)d_out;

    pack_labels_kernel<<<(N + 255) / 256, 256>>>(img, tex);

    dim3 grid(N / TILE, N / TILE);
    theta_loss_kernel<<<grid, 256>>>(F, G);

    finalize_kernel<<<1, 256>>>(F, G, B, out);
}

// round 2
// speedup vs baseline: 1.9072x; 1.9072x over previous
#include <cuda_runtime.h>
#include <cuda_bf16.h>

#define N 8192
#define BITS 16
#define NLAB 81
#define GAMMA 0.5f
#define ETA 0.5f
#define TILE 128
#define NCTA ((N/TILE)*(N/TILE))   // 4096
#define NPROLOG (N/8)              // 1024

// c = 0.5 * log2(e): accumulate c*theta so softplus(theta/2) = ln2 * log2(1 + exp2(c*theta))
#define CSCALE  0.72134752044448170368f
#define LN2F    0.69314718055994530942f
#define TWO_LN2 1.38629436111989061884f

typedef unsigned long long u64;

// scratch
__device__ uint4  g_imgp[N];        // packed img labels: {bits0-31, bits32-63, bits64-80, 0}
__device__ uint4  g_texp[N];
__device__ double g_partial[NCTA];  // theta-tile partials
__device__ double g_partial2[NPROLOG]; // term2/term3 partials

#define FMA2(acc, a, b) asm("fma.rn.f32x2 %0, %1, %2, %0;" : "+l"(acc) : "l"(a), "l"(b))
#define ADD2(acc, v)    asm("add.rn.f32x2 %0, %0, %1;"     : "+l"(acc) : "l"(v))
#define DUP2(d, s)      asm("mov.b64 %0, {%1, %1};"        : "=l"(d)   : "f"(s))
#define PACK2(d, lo, hi)   asm("mov.b64 %0, {%1, %2};"     : "=l"(d)   : "f"(lo), "f"(hi))
#define UNPACK2(lo, hi, s) asm("mov.b64 {%0, %1}, %2;"     : "=f"(lo), "=f"(hi) : "l"(s))
#define EX2(d, s) asm("ex2.approx.f32 %0, %1;" : "=f"(d) : "f"(s))
#define LG2(d, s) asm("lg2.approx.f32 %0, %1;" : "=f"(d) : "f"(s))

// ---------------------------------------------------------------------------
// Prolog: one warp per row. Ballot-packs the 81 binary labels (coalesced) and
// computes the per-row quantization/balance contribution; one double per CTA.
// ---------------------------------------------------------------------------
__global__ __launch_bounds__(256)
void prolog_kernel(const int* __restrict__ img, const int* __restrict__ tex,
                   const float* __restrict__ F, const float* __restrict__ G,
                   const float* __restrict__ Bq) {
    const int w    = threadIdx.x >> 5;
    const int lane = threadIdx.x & 31;
    const int row  = blockIdx.x * 8 + w;

    const int* ir = img + (long long)row * NLAB;
    const int* tr = tex + (long long)row * NLAB;
    unsigned i0 = __ballot_sync(0xffffffffu, ir[lane] != 0);
    unsigned i1 = __ballot_sync(0xffffffffu, ir[32 + lane] != 0);
    unsigned i2 = __ballot_sync(0xffffffffu, (lane < NLAB - 64) ? (ir[64 + lane] != 0) : false);
    unsigned t0 = __ballot_sync(0xffffffffu, tr[lane] != 0);
    unsigned t1 = __ballot_sync(0xffffffffu, tr[32 + lane] != 0);
    unsigned t2 = __ballot_sync(0xffffffffu, (lane < NLAB - 64) ? (tr[64 + lane] != 0) : false);
    if (lane == 0) {
        g_imgp[row] = make_uint4(i0, i1, i2, 0u);
        g_texp[row] = make_uint4(t0, t1, t2, 0u);
    }

    // term2/term3 for this row (lanes 0..15 hold the 16 bit positions)
    float f = 0.0f, g = 0.0f, b = 0.0f;
    if (lane < BITS) {
        f = F[(long long)row * BITS + lane];
        g = G[(long long)row * BITS + lane];
        b = Bq[(long long)row * BITS + lane];
    }
    float df = b - f, dg = b - g;
    float q  = df * df + dg * dg;
    float sf = f, sg = g;
#pragma unroll
    for (int off = 8; off > 0; off >>= 1) {
        q  += __shfl_xor_sync(0xffffffffu, q,  off);
        sf += __shfl_xor_sync(0xffffffffu, sf, off);
        sg += __shfl_xor_sync(0xffffffffu, sg, off);
    }

    __shared__ double wacc[8];
    if (lane == 0)
        wacc[w] = (double)(GAMMA * q + ETA * (sf * sf + sg * sg));
    __syncthreads();
    if (threadIdx.x == 0) {
        double s = 0.0;
#pragma unroll
        for (int i = 0; i < 8; i++) s += wacc[i];
        g_partial2[blockIdx.x] = s;
    }
}

// ---------------------------------------------------------------------------
// Main pass: 128x128 theta tile per CTA, 16x16 threads, 8x8 outputs/thread
// computed as 8x4 packed f32x2 pairs via fma.rn.f32x2. F tile is pre-scaled
// by CSCALE so acc = c*theta directly.
// ---------------------------------------------------------------------------
__global__ __launch_bounds__(256, 2)
void theta_loss_kernel(const float* __restrict__ F,
                       const float* __restrict__ G) {
    __shared__ float sF[BITS][TILE];   // k-major, pre-scaled by CSCALE
    __shared__ float sG[BITS][TILE];   // k-major
    __shared__ uint4 sIlab[TILE];
    __shared__ uint4 sTlab[TILE];
    __shared__ float warp_sum[8];

    const int tid = threadIdx.x;
    const int i0 = blockIdx.y * TILE;
    const int t0 = blockIdx.x * TILE;

    {
        int r = tid >> 1;
        int h = (tid & 1) * 8;
        const float4* fp = (const float4*)(F + (long long)(i0 + r) * BITS + h);
        const float4* gp = (const float4*)(G + (long long)(t0 + r) * BITS + h);
        float4 f0 = fp[0], f1 = fp[1];
        float4 g0 = gp[0], g1 = gp[1];
        sF[h + 0][r] = f0.x * CSCALE; sF[h + 1][r] = f0.y * CSCALE;
        sF[h + 2][r] = f0.z * CSCALE; sF[h + 3][r] = f0.w * CSCALE;
        sF[h + 4][r] = f1.x * CSCALE; sF[h + 5][r] = f1.y * CSCALE;
        sF[h + 6][r] = f1.z * CSCALE; sF[h + 7][r] = f1.w * CSCALE;
        sG[h + 0][r] = g0.x; sG[h + 1][r] = g0.y; sG[h + 2][r] = g0.z; sG[h + 3][r] = g0.w;
        sG[h + 4][r] = g1.x; sG[h + 5][r] = g1.y; sG[h + 6][r] = g1.z; sG[h + 7][r] = g1.w;
    }
    if (tid < TILE) {
        sIlab[tid] = g_imgp[i0 + tid];
    } else {
        sTlab[tid - TILE] = g_texp[t0 + (tid - TILE)];
    }
    __syncthreads();

    const int ty = tid >> 4;
    const int tx = tid & 15;

    u64 acc2[8][4];
#pragma unroll
    for (int a = 0; a < 8; a++)
#pragma unroll
        for (int b = 0; b < 4; b++) acc2[a][b] = 0ull;

#pragma unroll
    for (int k = 0; k < BITS; k++) {
        float4 a0 = *(const float4*)&sF[k][ty * 8];
        float4 a1 = *(const float4*)&sF[k][ty * 8 + 4];
        ulonglong2 bv0 = *(const ulonglong2*)&sG[k][tx * 8];
        ulonglong2 bv1 = *(const ulonglong2*)&sG[k][tx * 8 + 4];
        float av[8] = {a0.x, a0.y, a0.z, a0.w, a1.x, a1.y, a1.z, a1.w};
        u64 ad[8];
#pragma unroll
        for (int a = 0; a < 8; a++) DUP2(ad[a], av[a]);
#pragma unroll
        for (int a = 0; a < 8; a++) {
            FMA2(acc2[a][0], ad[a], bv0.x);
            FMA2(acc2[a][1], ad[a], bv0.y);
            FMA2(acc2[a][2], ad[a], bv1.x);
            FMA2(acc2[a][3], ad[a], bv1.y);
        }
    }

    // --- epilogue: acc = c*theta.  softplus-sum in log2 domain + masked sum ---
    uint4 il[8];
#pragma unroll
    for (int a = 0; a < 8; a++) il[a] = sIlab[ty * 8 + a];

    u64 slog2 = 0ull;          // packed pair of log2-domain accumulators
    float sthA = 0.0f, sthB = 0.0f;   // masked c*theta accumulators

#pragma unroll
    for (int b = 0; b < 4; b++) {
        uint4 tl0 = sTlab[tx * 8 + 2 * b];
        uint4 tl1 = sTlab[tx * 8 + 2 * b + 1];
#pragma unroll
        for (int a = 0; a < 8; a++) {
            float th0, th1;
            UNPACK2(th0, th1, acc2[a][b]);
            float e0, e1;
            EX2(e0, th0);
            EX2(e1, th1);
            float p0 = 1.0f + e0;
            float p1 = 1.0f + e1;
            float l0, l1;
            LG2(l0, p0);
            LG2(l1, p1);
            u64 l2;
            PACK2(l2, l0, l1);
            ADD2(slog2, l2);
            bool s0 = (((il[a].x & tl0.x) | (il[a].y & tl0.y) | (il[a].z & tl0.z)) != 0u);
            bool s1 = (((il[a].x & tl1.x) | (il[a].y & tl1.y) | (il[a].z & tl1.z)) != 0u);
            sthA += s0 ? th0 : 0.0f;
            sthB += s1 ? th1 : 0.0f;
        }
    }

    float slo, shi;
    UNPACK2(slo, shi, slog2);
    // softplus contribution = ln2 * sum(log2(...)); masked theta = (c*theta)/c = 2ln2*(c*theta)
    float sum = LN2F * (slo + shi) - TWO_LN2 * (sthA + sthB);

#pragma unroll
    for (int off = 16; off > 0; off >>= 1)
        sum += __shfl_down_sync(0xffffffffu, sum, off);
    if ((tid & 31) == 0) warp_sum[tid >> 5] = sum;
    __syncthreads();
    if (tid == 0) {
        float s = 0.0f;
#pragma unroll
        for (int w = 0; w < 8; w++) s += warp_sum[w];
        g_partial[blockIdx.y * gridDim.x + blockIdx.x] = (double)s;
    }
}

// ---------------------------------------------------------------------------
// Finalize: one CTA sums all partials in fixed order, writes the scalar.
// ---------------------------------------------------------------------------
__global__ void finalize_kernel(float* __restrict__ out) {
    __shared__ double sh[256];
    int t = threadIdx.x;
    double acc = 0.0;
    for (int p = t; p < NCTA; p += 256) acc += g_partial[p];
    for (int p = t; p < NPROLOG; p += 256) acc += g_partial2[p];
    sh[t] = acc;
    __syncthreads();
    for (int s = 128; s > 0; s >>= 1) {
        if (t < s) sh[t] += sh[t + s];
        __syncthreads();
    }
    if (t == 0) out[0] = (float)sh[0];
}

// ---------------------------------------------------------------------------
extern "C" void kernel_launch(void* const* d_in, const int* in_sizes, int n_in,
                              void* d_out, int out_size) {
    const float* F = (const float*)d_in[0];
    const float* G = (const float*)d_in[1];
    const float* B = (const float*)d_in[2];
    const int* img = (const int*)d_in[3];
    const int* tex = (const int*)d_in[4];
    float* out = (float*)d_out;

    prolog_kernel<<<NPROLOG, 256>>>(img, tex, F, G, B);

    dim3 grid(N / TILE, N / TILE);
    theta_loss_kernel<<<grid, 256>>>(F, G);

    finalize_kernel<<<1, 256>>>(out);
}

// round 4
// speedup vs baseline: 3.6869x; 1.9332x over previous
#include <cuda_runtime.h>
#include <cuda_bf16.h>
#include <cstdint>

#define N 8192
#define BITS 16
#define NLAB 81
#define GAMMA 0.5f
#define ETA 0.5f

#define TILE 128
#define GRID_X (N / TILE)            // 64
#define GRID_Y (N / TILE)            // 64
#define NCTA (GRID_X * GRID_Y)       // 4096
#define NPROLOG (N / 8)              // 1024

// c = 0.5*log2(e): accumulate c*theta so softplus(theta/2) = ln2*log2(1+exp2(c*theta))
#define CSCALE  0.72134752044448170368f
#define LN2F    0.69314718055994530942f
#define TWO_LN2 1.38629436111989061884f

typedef unsigned long long u64;

// ---- device scratch ----
__device__ __nv_bfloat16 g_Fb[N * BITS];   // bf16(CSCALE * F)
__device__ __nv_bfloat16 g_Gb[N * BITS];   // bf16(G)
__device__ uint4  g_imgp[N];               // packed labels {b0-31,b32-63,b64-80,0}
__device__ uint4  g_texp[N];
__device__ double g_partial[NCTA];
__device__ double g_partial2[NPROLOG];

__device__ __forceinline__ uint32_t smem_u32(const void* p) {
    uint32_t a;
    asm("{ .reg .u64 t; cvta.to.shared.u64 t, %1; cvt.u32.u64 %0, t; }" : "=r"(a) : "l"(p));
    return a;
}
#define EX2(d, s) asm("ex2.approx.f32 %0, %1;" : "=f"(d) : "f"(s))
#define LG2(d, s) asm("lg2.approx.f32 %0, %1;" : "=f"(d) : "f"(s))

#define LDSM_X4(r0, r1, r2, r3, addr) \
    asm volatile("ldmatrix.sync.aligned.m8n8.x4.shared.b16 {%0,%1,%2,%3}, [%4];" \
                 : "=r"(r0), "=r"(r1), "=r"(r2), "=r"(r3) : "r"(addr))

__device__ __forceinline__ void mma16816(float& d0, float& d1, float& d2, float& d3,
                                         uint32_t a0, uint32_t a1, uint32_t a2, uint32_t a3,
                                         uint32_t b0, uint32_t b1) {
    asm volatile(
        "mma.sync.aligned.m16n8k16.row.col.f32.bf16.bf16.f32 "
        "{%0,%1,%2,%3}, {%4,%5,%6,%7}, {%8,%9}, {%10,%11,%12,%13};"
        : "=f"(d0), "=f"(d1), "=f"(d2), "=f"(d3)
        : "r"(a0), "r"(a1), "r"(a2), "r"(a3), "r"(b0), "r"(b1),
          "f"(0.0f), "f"(0.0f), "f"(0.0f), "f"(0.0f));
}

// ---------------------------------------------------------------------------
// Prolog: one warp per row. Ballot-packs labels, emits bf16(c*F), bf16(G),
// and per-row quantization/balance partials.
// ---------------------------------------------------------------------------
__global__ __launch_bounds__(256)
void prolog_kernel(const int* __restrict__ img, const int* __restrict__ tex,
                   const float* __restrict__ F, const float* __restrict__ G,
                   const float* __restrict__ Bq) {
    const int w    = threadIdx.x >> 5;
    const int lane = threadIdx.x & 31;
    const int row  = blockIdx.x * 8 + w;

    const int* ir = img + (long long)row * NLAB;
    const int* tr = tex + (long long)row * NLAB;
    unsigned i0 = __ballot_sync(0xffffffffu, ir[lane] != 0);
    unsigned i1 = __ballot_sync(0xffffffffu, ir[32 + lane] != 0);
    unsigned i2 = __ballot_sync(0xffffffffu, (lane < NLAB - 64) ? (ir[64 + lane] != 0) : false);
    unsigned t0 = __ballot_sync(0xffffffffu, tr[lane] != 0);
    unsigned t1 = __ballot_sync(0xffffffffu, tr[32 + lane] != 0);
    unsigned t2 = __ballot_sync(0xffffffffu, (lane < NLAB - 64) ? (tr[64 + lane] != 0) : false);
    if (lane == 0) {
        g_imgp[row] = make_uint4(i0, i1, i2, 0u);
        g_texp[row] = make_uint4(t0, t1, t2, 0u);
    }

    float f = 0.0f, g = 0.0f, b = 0.0f;
    if (lane < BITS) {
        f = F[(long long)row * BITS + lane];
        g = G[(long long)row * BITS + lane];
        b = Bq[(long long)row * BITS + lane];
        g_Fb[(long long)row * BITS + lane] = __float2bfloat16_rn(f * CSCALE);
        g_Gb[(long long)row * BITS + lane] = __float2bfloat16_rn(g);
    }
    float df = b - f, dg = b - g;
    float q  = df * df + dg * dg;
    float sf = f, sg = g;
#pragma unroll
    for (int off = 8; off > 0; off >>= 1) {
        q  += __shfl_xor_sync(0xffffffffu, q,  off);
        sf += __shfl_xor_sync(0xffffffffu, sf, off);
        sg += __shfl_xor_sync(0xffffffffu, sg, off);
    }

    __shared__ double wacc[8];
    if (lane == 0)
        wacc[w] = (double)(GAMMA * q + ETA * (sf * sf + sg * sg));
    __syncthreads();
    if (threadIdx.x == 0) {
        double s = 0.0;
#pragma unroll
        for (int i = 0; i < 8; i++) s += wacc[i];
        g_partial2[blockIdx.x] = s;
    }
}

// ---------------------------------------------------------------------------
// Main: 128x128 theta tile per CTA via mma.sync m16n8k16 bf16. Warp w owns
// rows [w*16, w*16+16). Per iteration: one ldmatrix.x4 (two 8-col B tiles),
// two mma, then immediate softplus+mask epilogue on the 8 accumulators.
// ---------------------------------------------------------------------------
__global__ __launch_bounds__(256)
void theta_loss_kernel() {
    __shared__ __nv_bfloat16 sA[TILE * BITS];   // rows i, 32B/row, 4KB
    __shared__ __nv_bfloat16 sB[TILE * BITS];   // rows t, 32B/row, 4KB
    __shared__ uint4 sIlab[TILE];
    __shared__ uint4 sTlab[TILE];
    __shared__ float warp_sum[8];

    const int tid  = threadIdx.x;
    const int wid  = tid >> 5;
    const int lane = tid & 31;
    const int i0   = blockIdx.y * TILE;
    const int t0   = blockIdx.x * TILE;

    // --- fill operand tiles (16B per thread per tile) ---
    {
        const int r = tid >> 1;
        const int h = (tid & 1) * 8;
        *(uint4*)(sA + r * BITS + h) = *(const uint4*)(g_Fb + (long long)(i0 + r) * BITS + h);
        *(uint4*)(sB + r * BITS + h) = *(const uint4*)(g_Gb + (long long)(t0 + r) * BITS + h);
    }
    if (tid < TILE) sIlab[tid] = g_imgp[i0 + tid];
    else            sTlab[tid - TILE] = g_texp[t0 + (tid - TILE)];
    __syncthreads();

    const int rbase = wid * 16;

    // A fragment: lanes 0-7 rows 0-7 k0-7, 8-15 rows 8-15 k0-7,
    //             16-23 rows 0-7 k8-15, 24-31 rows 8-15 k8-15
    uint32_t a0, a1, a2, a3;
    {
        uint32_t addr = smem_u32(sA) + (uint32_t)((rbase + (lane & 15)) * 32 + ((lane >> 4) << 4));
        LDSM_X4(a0, a1, a2, a3, addr);
    }

    const uint32_t sBu = smem_u32(sB);
    const int qc = (lane & 3) * 2;          // col offset within 8-col tile
    const uint4 il_lo = sIlab[rbase + (lane >> 2)];
    const uint4 il_hi = sIlab[rbase + (lane >> 2) + 8];

    float lsum = 0.0f;   // sum log2(1+exp2(c*theta))
    float msum = 0.0f;   // sum c*theta over sim pairs

#pragma unroll
    for (int it = 0; it < 8; it++) {
        const int n0 = it * 16;
        // B fragments for two 8-col tiles:
        //  m0: n0..n0+7 k0-7 | m1: n0..+7 k8-15 | m2: n0+8.. k0-7 | m3: n0+8.. k8-15
        uint32_t b0, b1, b2, b3;
        {
            uint32_t addr = sBu + (uint32_t)((n0 + (lane & 7) + ((lane >> 4) << 3)) * 32
                                             + (((lane >> 3) & 1) << 4));
            LDSM_X4(b0, b1, b2, b3, addr);
        }

        float d0, d1, d2, d3, e0, e1, e2, e3;
        mma16816(d0, d1, d2, d3, a0, a1, a2, a3, b0, b1);   // cols n0 + qc, qc+1
        mma16816(e0, e1, e2, e3, a0, a1, a2, a3, b2, b3);   // cols n0+8 + qc, qc+1

        // --- softplus in log2 domain: product-of-quads trick (1 lg2 per 4) ---
        float x0, x1, x2, x3, y0, y1, y2, y3;
        EX2(x0, d0); EX2(x1, d1); EX2(x2, d2); EX2(x3, d3);
        EX2(y0, e0); EX2(y1, e1); EX2(y2, e2); EX2(y3, e3);
        float f01 = fmaf(x0, x1, x0 + x1);
        float f23 = fmaf(x2, x3, x2 + x3);
        float qx  = fmaf(f01, f23, f01 + f23) + 1.0f;
        float g01 = fmaf(y0, y1, y0 + y1);
        float g23 = fmaf(y2, y3, y2 + y3);
        float qy  = fmaf(g01, g23, g01 + g23) + 1.0f;
        float lx, ly;
        LG2(lx, qx); LG2(ly, qy);
        lsum += lx + ly;

        // --- sim masks ---
        const uint4 ta = sTlab[n0 + qc];
        const uint4 tb = sTlab[n0 + qc + 1];
        const uint4 tc = sTlab[n0 + qc + 8];
        const uint4 td = sTlab[n0 + qc + 9];

        unsigned m;
        m = (il_lo.x & ta.x) | (il_lo.y & ta.y) | (il_lo.z & ta.z); msum += m ? d0 : 0.0f;
        m = (il_lo.x & tb.x) | (il_lo.y & tb.y) | (il_lo.z & tb.z); msum += m ? d1 : 0.0f;
        m = (il_hi.x & ta.x) | (il_hi.y & ta.y) | (il_hi.z & ta.z); msum += m ? d2 : 0.0f;
        m = (il_hi.x & tb.x) | (il_hi.y & tb.y) | (il_hi.z & tb.z); msum += m ? d3 : 0.0f;
        m = (il_lo.x & tc.x) | (il_lo.y & tc.y) | (il_lo.z & tc.z); msum += m ? e0 : 0.0f;
        m = (il_lo.x & td.x) | (il_lo.y & td.y) | (il_lo.z & td.z); msum += m ? e1 : 0.0f;
        m = (il_hi.x & tc.x) | (il_hi.y & tc.y) | (il_hi.z & tc.z); msum += m ? e2 : 0.0f;
        m = (il_hi.x & td.x) | (il_hi.y & td.y) | (il_hi.z & td.z); msum += m ? e3 : 0.0f;
    }

    float sum = LN2F * lsum - TWO_LN2 * msum;
#pragma unroll
    for (int off = 16; off > 0; off >>= 1)
        sum += __shfl_down_sync(0xffffffffu, sum, off);
    if (lane == 0) warp_sum[wid] = sum;
    __syncthreads();
    if (tid == 0) {
        float s = 0.0f;
#pragma unroll
        for (int w = 0; w < 8; w++) s += warp_sum[w];
        g_partial[blockIdx.y * gridDim.x + blockIdx.x] = (double)s;
    }
}

// ---------------------------------------------------------------------------
// Finalize: fixed-order sum of all partials.
// ---------------------------------------------------------------------------
__global__ void finalize_kernel(float* __restrict__ out) {
    __shared__ double sh[256];
    int t = threadIdx.x;
    double acc = 0.0;
    for (int p = t; p < NCTA; p += 256) acc += g_partial[p];
    for (int p = t; p < NPROLOG; p += 256) acc += g_partial2[p];
    sh[t] = acc;
    __syncthreads();
    for (int s = 128; s > 0; s >>= 1) {
        if (t < s) sh[t] += sh[t + s];
        __syncthreads();
    }
    if (t == 0) out[0] = (float)sh[0];
}

// ---------------------------------------------------------------------------
extern "C" void kernel_launch(void* const* d_in, const int* in_sizes, int n_in,
                              void* d_out, int out_size) {
    const float* F = (const float*)d_in[0];
    const float* G = (const float*)d_in[1];
    const float* B = (const float*)d_in[2];
    const int* img = (const int*)d_in[3];
    const int* tex = (const int*)d_in[4];
    float* out = (float*)d_out;

    prolog_kernel<<<NPROLOG, 256>>>(img, tex, F, G, B);

    dim3 grid(GRID_X, GRID_Y);
    theta_loss_kernel<<<grid, 256>>>();

    finalize_kernel<<<1, 256>>>(out);
}